// round 10
// baseline (speedup 1.0000x reference)
#include <cuda_runtime.h>
#include <cuda_fp16.h>
#include <cstdint>
#include <math.h>

#define CC 256          // channels
#define GG_MAX 4096     // graphs
#define N_MAX 500000    // nodes

__device__ float g_aw[N_MAX + 256];
__device__ __align__(16) __half g_Wth[CC * CC];   // W1a^T fp16: [n][k]
__device__ float g_comb[GG_MAX * 3 * CC];
__device__ float g_hidden[GG_MAX * CC];
__device__ int   g_is64;

// ---------------------------------------------------------------------------
// helpers
// ---------------------------------------------------------------------------
__device__ __forceinline__ uint32_t smem_u32(const void* p) {
    uint32_t a;
    asm("{ .reg .u64 t; cvta.to.shared.u64 t, %1; cvt.u32.u64 %0, t; }" : "=r"(a) : "l"(p));
    return a;
}

#define LDMX4(r0, r1, r2, r3, addr) \
    asm volatile("ldmatrix.sync.aligned.m8n8.x4.shared.b16 {%0,%1,%2,%3}, [%4];" \
        : "=r"(r0), "=r"(r1), "=r"(r2), "=r"(r3) : "r"(addr))

__device__ __forceinline__ void mma_f16(float* c, const uint32_t* a, uint32_t b0, uint32_t b1) {
    asm volatile(
        "mma.sync.aligned.m16n8k16.row.col.f32.f16.f16.f32 "
        "{%0,%1,%2,%3}, {%4,%5,%6,%7}, {%8,%9}, {%0,%1,%2,%3};"
        : "+f"(c[0]), "+f"(c[1]), "+f"(c[2]), "+f"(c[3])
        : "r"(a[0]), "r"(a[1]), "r"(a[2]), "r"(a[3]), "r"(b0), "r"(b1));
}

#define CP_COMMIT() asm volatile("cp.async.commit_group;" ::: "memory")
#define CP_WAIT1()  asm volatile("cp.async.wait_group 1;" ::: "memory")

// ---------------------------------------------------------------------------
// batch dtype detection (int32 vs int64 view; sorted-ness discriminates)
// ---------------------------------------------------------------------------
__global__ void k0_init() { g_is64 = 0; }
__global__ void k0_detect(const int* __restrict__ b32, int N) {
    int i = blockIdx.x * blockDim.x + threadIdx.x;
    if (i < N - 1) {
        int a = b32[i], b = b32[i + 1];
        if (a > b || a < 0 || b < 0) g_is64 = 1;
    }
}
__device__ __forceinline__ long long bval(const void* b, int i) {
    if (g_is64) return ((const long long*)b)[i];
    return (long long)((const int*)b)[i];
}

// ---------------------------------------------------------------------------
// W1a -> transposed fp16
// ---------------------------------------------------------------------------
__global__ void k_wt(const float* __restrict__ W1a) {
    int n = blockIdx.x, k = threadIdx.x;
    g_Wth[n * CC + k] = __float2half(W1a[k * CC + n]);
}

// ---------------------------------------------------------------------------
// K1: fused attention MLP, fp16 mma.sync, persistent 512-thread CTAs.
// 16 warps = 8 n-groups (n32) x 2 k-groups (k128). Per warp: B frags for its
// (n32, k128) block = 64 regs, loaded once from global (analytic frag layout).
// A-LDS is 1 wf/mma (round-8 ratio) with 4 warps/SMSP (round-9 hiding).
// relu is nonlinear -> k-partials summed in smem before the epilogue:
// kg=0 stores acc (float4, lane-interleaved), kg=1 adds + epilogue.
// 2-stage A32 cp.async ring + single A16 buffer.
// ---------------------------------------------------------------------------
#define TILE_M    32
#define NTHREADS  512
#define RING_OFF  0            // 2 x 32768
#define STG_BYTES 32768
#define A16_OFF   65536        // 16384
#define SACC_OFF  81920        // 8 ngrp * 8 f4 * 32 lanes * 16B = 32768
#define SB1_OFF   114688
#define SW2_OFF   115712
#define PBUF_OFF  116736       // 8*32 floats
#define K1_SMEM   117760

__device__ __forceinline__ void k1_load_stage(uint32_t sb, const float* __restrict__ x,
                                              int m0, int N, int s) {
    const int tid = threadIdx.x;
    #pragma unroll
    for (int u = 0; u < 4; ++u) {
        int idx = tid + u * NTHREADS;       // 2048 16B-chunks: 32 rows x 64 f4
        int row = idx >> 6, c4 = idx & 63;
        int node = m0 + row;
        const float* src = x + (size_t)(node < N ? node : 0) * CC + c4 * 4;
        uint32_t dst = sb + RING_OFF + s * STG_BYTES + row * 1024 + c4 * 16;
        uint32_t sz = (node < N) ? 16u : 0u;
        asm volatile("cp.async.cg.shared.global [%0], [%1], 16, %2;"
                     :: "r"(dst), "l"(src), "r"(sz));
    }
}

__global__ void __launch_bounds__(NTHREADS, 1) k1_fp16(
    const float* __restrict__ x, const float* __restrict__ b1a,
    const float* __restrict__ W2a, const float* __restrict__ b2a,
    int N, int nTiles)
{
    extern __shared__ char sm[];
    const uint32_t sb = smem_u32(sm);
    float*  sB1   = (float*)(sm + SB1_OFF);
    float*  sW2   = (float*)(sm + SW2_OFF);
    float*  pbuf  = (float*)(sm + PBUF_OFF);
    float4* sacc4 = (float4*)(sm + SACC_OFF);

    const int tid  = threadIdx.x;
    const int lane = tid & 31;
    const int w    = tid >> 5;        // 0..15
    const int kg   = w & 1;           // k-group: k in [kg*128, kg*128+128)
    const int ng   = w >> 1;          // n-group: cols ng*32 .. +31
    const int ncol0 = ng * 32;

    if (tid < CC) { sB1[tid] = b1a[tid]; sW2[tid] = W2a[tid]; }
    const float b2 = b2a[0];

    const int lrow   = lane & 15;
    const int lchunk = lane >> 4;
    const int qr = lane >> 2, qc = lane & 3;

    // --- prologue: B fragments straight from global (one time) ---
    // thread l holds B[n0 + bq*16 + l/4 (+8)][kg*128 + ks*16 + 2*(l%4) (+8,+1)]
    uint32_t breg[8][2][4];
    {
        const __half* bb = g_Wth + (size_t)(ncol0 + (lane >> 2)) * CC
                         + (lane & 3) * 2 + kg * 128;
        #pragma unroll
        for (int ks = 0; ks < 8; ++ks) {
            const __half* base = bb + ks * 16;
            #pragma unroll
            for (int bq = 0; bq < 2; ++bq) {
                const __half* p = base + bq * 16 * CC;
                breg[ks][bq][0] = *(const uint32_t*)(p);
                breg[ks][bq][1] = *(const uint32_t*)(p + 8 * CC);
                breg[ks][bq][2] = *(const uint32_t*)(p + 8);
                breg[ks][bq][3] = *(const uint32_t*)(p + 8 * CC + 8);
            }
        }
    }

    // --- prime 2 ring stages (uniform commits) ---
    #pragma unroll
    for (int j = 0; j < 2; ++j) {
        int tj = blockIdx.x + j * gridDim.x;
        if (tj < nTiles) k1_load_stage(sb, x, tj * TILE_M, N, j);
        CP_COMMIT();
    }

    int i = 0;
    for (int t = blockIdx.x; t < nTiles; t += gridDim.x, ++i) {
        const int s  = i & 1;
        const int m0 = t * TILE_M;

        CP_WAIT1();               // stage s (tile t) resident
        __syncthreads();          // visible to all; A16/sacc/pbuf free

        // convert A32[s] -> A16 (swizzled fp16)
        #pragma unroll
        for (int u = 0; u < 2; ++u) {
            int idx = tid + u * NTHREADS;  // 1024 fp16 16B-chunks: 32 rows x 32
            int row = idx >> 5, c = idx & 31;
            const float4* src = (const float4*)(sm + RING_OFF + s * STG_BYTES + row * 1024 + c * 32);
            float4 v0 = src[0], v1 = src[1];
            __half2 h0 = __floats2half2_rn(v0.x, v0.y), h1 = __floats2half2_rn(v0.z, v0.w);
            __half2 h2 = __floats2half2_rn(v1.x, v1.y), h3 = __floats2half2_rn(v1.z, v1.w);
            uint4 u4;
            u4.x = *(uint32_t*)&h0; u4.y = *(uint32_t*)&h1;
            u4.z = *(uint32_t*)&h2; u4.w = *(uint32_t*)&h3;
            *(uint4*)(sm + A16_OFF + row * 512 + ((c ^ (row & 7)) << 4)) = u4;
        }
        __syncthreads();          // A16 ready; A32[s] free

        // prefetch tile t+2 into stage s (uniform commit)
        {
            int tn = t + 2 * gridDim.x;
            if (tn < nTiles) k1_load_stage(sb, x, tn * TILE_M, N, s);
            CP_COMMIT();
        }

        // mma: warp computes m32 x n32 over its k128; B from registers
        float acc[2][4][4];
        #pragma unroll
        for (int mt = 0; mt < 2; ++mt)
            #pragma unroll
            for (int j = 0; j < 4; ++j) {
                acc[mt][j][0] = 0.f; acc[mt][j][1] = 0.f;
                acc[mt][j][2] = 0.f; acc[mt][j][3] = 0.f;
            }
        #pragma unroll
        for (int ks = 0; ks < 8; ++ks) {
            const int kc = (kg * 8 + ks) * 2 + lchunk;
            uint32_t a[2][4];
            #pragma unroll
            for (int mt = 0; mt < 2; ++mt) {
                int row = mt * 16 + lrow;
                uint32_t ad = sb + A16_OFF + row * 512 + ((kc ^ (row & 7)) << 4);
                LDMX4(a[mt][0], a[mt][1], a[mt][2], a[mt][3], ad);
            }
            #pragma unroll
            for (int mt = 0; mt < 2; ++mt)
                #pragma unroll
                for (int bq = 0; bq < 2; ++bq) {
                    mma_f16(acc[mt][2 * bq],     a[mt], breg[ks][bq][0], breg[ks][bq][2]);
                    mma_f16(acc[mt][2 * bq + 1], a[mt], breg[ks][bq][1], breg[ks][bq][3]);
                }
        }

        // k-partial exchange: kg=0 stores, kg=1 adds + epilogue
        if (kg == 0) {
            #pragma unroll
            for (int mt = 0; mt < 2; ++mt)
                #pragma unroll
                for (int j = 0; j < 4; ++j)
                    sacc4[(ng * 8 + mt * 4 + j) * 32 + lane] = *(float4*)acc[mt][j];
        }
        __syncthreads();

        if (kg == 1) {
            float p[4] = {0.f, 0.f, 0.f, 0.f};   // rows qr, qr+8, 16+qr, 24+qr
            #pragma unroll
            for (int mt = 0; mt < 2; ++mt)
                #pragma unroll
                for (int j = 0; j < 4; ++j) {
                    float4 o = sacc4[(ng * 8 + mt * 4 + j) * 32 + lane];
                    float a0 = acc[mt][j][0] + o.x;
                    float a1 = acc[mt][j][1] + o.y;
                    float a2 = acc[mt][j][2] + o.z;
                    float a3 = acc[mt][j][3] + o.w;
                    int col = ncol0 + j * 8 + qc * 2;
                    float bA = sB1[col], bB = sB1[col + 1];
                    float wA = sW2[col], wB = sW2[col + 1];
                    p[mt * 2]     += fmaxf(a0 + bA, 0.f) * wA + fmaxf(a1 + bB, 0.f) * wB;
                    p[mt * 2 + 1] += fmaxf(a2 + bA, 0.f) * wA + fmaxf(a3 + bB, 0.f) * wB;
                }
            #pragma unroll
            for (int j = 0; j < 4; ++j) {
                p[j] += __shfl_xor_sync(0xffffffffu, p[j], 1);
                p[j] += __shfl_xor_sync(0xffffffffu, p[j], 2);
            }
            if (qc == 0) {
                pbuf[ng * 32 + qr]      = p[0];
                pbuf[ng * 32 + qr + 8]  = p[1];
                pbuf[ng * 32 + qr + 16] = p[2];
                pbuf[ng * 32 + qr + 24] = p[3];
            }
        }
        __syncthreads();
        if (tid < 32) {
            float ssum = 0.f;
            #pragma unroll
            for (int k = 0; k < 8; ++k) ssum += pbuf[k * 32 + tid];
            int node = m0 + tid;
            if (node < N) g_aw[node] = 1.f / (1.f + expf(-(ssum + b2)));
        }
    }
}

// ---------------------------------------------------------------------------
// K2: segment pooling. 512 threads = 64 float4-channel groups x 8 row lanes.
// batch sorted -> contiguous segments; binary-search bounds; no atomics.
// ---------------------------------------------------------------------------
__global__ void __launch_bounds__(512) k2_pool(
    const float* __restrict__ x, const void* __restrict__ batch, int N)
{
    const int g = blockIdx.x;
    __shared__ int sR[2];
    __shared__ float4 red[3][8][64];
    const int tid = threadIdx.x;
    const int cq  = tid & 63;
    const int r   = tid >> 6;     // 0..7

    if (tid == 0) {
        int lo = 0, hi = N;
        while (lo < hi) { int mid = (lo + hi) >> 1; if (bval(batch, mid) < (long long)g) lo = mid + 1; else hi = mid; }
        sR[0] = lo;
        hi = N;
        while (lo < hi) { int mid = (lo + hi) >> 1; if (bval(batch, mid) < (long long)g + 1) lo = mid + 1; else hi = mid; }
        sR[1] = lo;
    }
    __syncthreads();
    const int s = sR[0], e = sR[1];

    float4 sum = make_float4(0.f, 0.f, 0.f, 0.f);
    float4 att = make_float4(0.f, 0.f, 0.f, 0.f);
    float4 mx  = make_float4(-INFINITY, -INFINITY, -INFINITY, -INFINITY);

    for (int i = s + r; i < e; i += 8) {
        float4 v = ((const float4*)(x + (size_t)i * CC))[cq];
        float wt = g_aw[i];
        sum.x += v.x; sum.y += v.y; sum.z += v.z; sum.w += v.w;
        att.x = fmaf(v.x, wt, att.x); att.y = fmaf(v.y, wt, att.y);
        att.z = fmaf(v.z, wt, att.z); att.w = fmaf(v.w, wt, att.w);
        mx.x = fmaxf(mx.x, v.x); mx.y = fmaxf(mx.y, v.y);
        mx.z = fmaxf(mx.z, v.z); mx.w = fmaxf(mx.w, v.w);
    }
    red[0][r][cq] = sum; red[1][r][cq] = att; red[2][r][cq] = mx;
    __syncthreads();

    if (r == 0) {
        #pragma unroll
        for (int k = 1; k < 8; ++k) {
            float4 a = red[0][k][cq], b = red[1][k][cq], m = red[2][k][cq];
            sum.x += a.x; sum.y += a.y; sum.z += a.z; sum.w += a.w;
            att.x += b.x; att.y += b.y; att.z += b.z; att.w += b.w;
            mx.x = fmaxf(mx.x, m.x); mx.y = fmaxf(mx.y, m.y);
            mx.z = fmaxf(mx.z, m.z); mx.w = fmaxf(mx.w, m.w);
        }
        float inv = 1.f / fmaxf((float)(e - s), 1.f);
        float4 mean = make_float4(sum.x * inv, sum.y * inv, sum.z * inv, sum.w * inv);
        float4 mxo = (e > s) ? mx : make_float4(0.f, 0.f, 0.f, 0.f);
        float* comb = g_comb + (size_t)g * (3 * CC);
        ((float4*)(comb))[cq]          = att;
        ((float4*)(comb + CC))[cq]     = mean;
        ((float4*)(comb + 2 * CC))[cq] = mxo;
    }
}

// ---------------------------------------------------------------------------
// K3: fp32 tiled GEMM with bias (+optional relu). 64x64 tile, 256 threads.
// ---------------------------------------------------------------------------
template <bool RELU>
__global__ void __launch_bounds__(256) k3_gemm(
    const float* __restrict__ A, const float* __restrict__ B,
    const float* __restrict__ bias, float* __restrict__ Out,
    int M, int K, int Nn)
{
    __shared__ float sA[16][68];
    __shared__ float sB[16][68];
    const int t  = threadIdx.x;
    const int tx = t & 15, ty = t >> 4;
    const int m0 = blockIdx.y * 64, n0 = blockIdx.x * 64;
    float acc[4][4] = {};

    for (int kt = 0; kt < K; kt += 16) {
        #pragma unroll
        for (int i = 0; i < 4; ++i) {
            int idx = t + i * 256;
            int m = idx >> 4, k = idx & 15;
            sA[k][m] = A[(size_t)(m0 + m) * K + kt + k];
        }
        #pragma unroll
        for (int i = 0; i < 4; ++i) {
            int idx = t + i * 256;
            int k = idx >> 6, n = idx & 63;
            sB[k][n] = B[(size_t)(kt + k) * Nn + n0 + n];
        }
        __syncthreads();
        #pragma unroll
        for (int kk = 0; kk < 16; ++kk) {
            float4 a4 = *(const float4*)&sA[kk][ty * 4];
            float4 b4 = *(const float4*)&sB[kk][tx * 4];
            float av[4] = {a4.x, a4.y, a4.z, a4.w};
            float bv[4] = {b4.x, b4.y, b4.z, b4.w};
            #pragma unroll
            for (int i = 0; i < 4; ++i)
                #pragma unroll
                for (int j = 0; j < 4; ++j)
                    acc[i][j] = fmaf(av[i], bv[j], acc[i][j]);
        }
        __syncthreads();
    }

    #pragma unroll
    for (int i = 0; i < 4; ++i) {
        int m = m0 + ty * 4 + i;
        #pragma unroll
        for (int j = 0; j < 4; ++j) {
            int n = n0 + tx * 4 + j;
            float v = acc[i][j] + bias[n];
            if (RELU) v = fmaxf(v, 0.f);
            Out[(size_t)m * Nn + n] = v;
        }
    }
}

// ---------------------------------------------------------------------------
// launch
// ---------------------------------------------------------------------------
extern "C" void kernel_launch(void* const* d_in, const int* in_sizes, int n_in,
                              void* d_out, int out_size)
{
    const float* x     = (const float*)d_in[0];
    const void*  batch = d_in[1];
    const float* W1a   = (const float*)d_in[2];
    const float* b1a   = (const float*)d_in[3];
    const float* W2a   = (const float*)d_in[4];
    const float* b2a   = (const float*)d_in[5];
    const float* W1f   = (const float*)d_in[6];
    const float* b1f   = (const float*)d_in[7];
    const float* W2f   = (const float*)d_in[8];
    const float* b2f   = (const float*)d_in[9];
    float* out = (float*)d_out;

    const int N = in_sizes[0] / CC;
    const int G = out_size / CC;

    float *comb_ptr = nullptr, *hid_ptr = nullptr;
    cudaGetSymbolAddress((void**)&comb_ptr, g_comb);
    cudaGetSymbolAddress((void**)&hid_ptr, g_hidden);

    cudaFuncSetAttribute(k1_fp16, cudaFuncAttributeMaxDynamicSharedMemorySize, K1_SMEM);

    k0_init<<<1, 1>>>();
    k0_detect<<<(N + 255) / 256, 256>>>((const int*)batch, N);
    k_wt<<<CC, CC>>>(W1a);

    const int nTiles = (N + TILE_M - 1) / TILE_M;
    const int grid = nTiles < 148 ? nTiles : 148;
    k1_fp16<<<grid, NTHREADS, K1_SMEM>>>(x, b1a, W2a, b2a, N, nTiles);
    k2_pool<<<G, 512>>>(x, batch, N);
    k3_gemm<true ><<<dim3(CC / 64, G / 64), 256>>>(comb_ptr, W1f, b1f, hid_ptr, G, 3 * CC, CC);
    k3_gemm<false><<<dim3(CC / 64, G / 64), 256>>>(hid_ptr,  W2f, b2f, out,     G, CC,     CC);
}

// round 11
// speedup vs baseline: 1.0704x; 1.0704x over previous
#include <cuda_runtime.h>
#include <cuda_fp16.h>
#include <cstdint>
#include <math.h>

#define CC 256          // channels
#define GG_MAX 4096     // graphs
#define N_MAX 500000    // nodes

__device__ float g_aw[N_MAX + 256];
__device__ __align__(16) __half g_Wth[CC * CC];   // W1a^T fp16: [n][k]
__device__ float g_comb[GG_MAX * 3 * CC];
__device__ float g_hidden[GG_MAX * CC];
__device__ int   g_is64;

// ---------------------------------------------------------------------------
// helpers
// ---------------------------------------------------------------------------
__device__ __forceinline__ uint32_t smem_u32(const void* p) {
    uint32_t a;
    asm("{ .reg .u64 t; cvta.to.shared.u64 t, %1; cvt.u32.u64 %0, t; }" : "=r"(a) : "l"(p));
    return a;
}

#define LDMX4(r0, r1, r2, r3, addr) \
    asm volatile("ldmatrix.sync.aligned.m8n8.x4.shared.b16 {%0,%1,%2,%3}, [%4];" \
        : "=r"(r0), "=r"(r1), "=r"(r2), "=r"(r3) : "r"(addr))

__device__ __forceinline__ void mma_f16(float* c, const uint32_t* a, uint32_t b0, uint32_t b1) {
    asm volatile(
        "mma.sync.aligned.m16n8k16.row.col.f32.f16.f16.f32 "
        "{%0,%1,%2,%3}, {%4,%5,%6,%7}, {%8,%9}, {%0,%1,%2,%3};"
        : "+f"(c[0]), "+f"(c[1]), "+f"(c[2]), "+f"(c[3])
        : "r"(a[0]), "r"(a[1]), "r"(a[2]), "r"(a[3]), "r"(b0), "r"(b1));
}

__device__ __forceinline__ uint32_t f2tf32(float f) {
    uint32_t r;
    asm("cvt.rna.tf32.f32 %0, %1;" : "=r"(r) : "f"(f));
    return r;
}

__device__ __forceinline__ void mma_tf32(float* c,
                                         uint32_t a0, uint32_t a1, uint32_t a2, uint32_t a3,
                                         uint32_t b0, uint32_t b1) {
    asm volatile(
        "mma.sync.aligned.m16n8k8.row.col.f32.tf32.tf32.f32 "
        "{%0,%1,%2,%3}, {%4,%5,%6,%7}, {%8,%9}, {%0,%1,%2,%3};\n"
        : "+f"(c[0]), "+f"(c[1]), "+f"(c[2]), "+f"(c[3])
        : "r"(a0), "r"(a1), "r"(a2), "r"(a3), "r"(b0), "r"(b1));
}

#define CP_COMMIT() asm volatile("cp.async.commit_group;" ::: "memory")
#define CP_WAIT1()  asm volatile("cp.async.wait_group 1;" ::: "memory")
#define CP_WAIT2()  asm volatile("cp.async.wait_group 2;" ::: "memory")

// ---------------------------------------------------------------------------
// batch dtype detection (int32 vs int64 view; sorted-ness discriminates)
// ---------------------------------------------------------------------------
__global__ void k0_init() { g_is64 = 0; }
__global__ void k0_detect(const int* __restrict__ b32, int N) {
    int i = blockIdx.x * blockDim.x + threadIdx.x;
    if (i < N - 1) {
        int a = b32[i], b = b32[i + 1];
        if (a > b || a < 0 || b < 0) g_is64 = 1;
    }
}
__device__ __forceinline__ long long bval(const void* b, int i) {
    if (g_is64) return ((const long long*)b)[i];
    return (long long)((const int*)b)[i];
}

// ---------------------------------------------------------------------------
// W1a -> transposed fp16
// ---------------------------------------------------------------------------
__global__ void k_wt(const float* __restrict__ W1a) {
    int n = blockIdx.x, k = threadIdx.x;
    g_Wth[n * CC + k] = __float2half(W1a[k * CC + n]);
}

// ---------------------------------------------------------------------------
// K1 (round-8 best: 209.3us): fused attention MLP, fp16 mma.sync, persistent
// CTAs. B frags in registers (warp n32 slice, 128 regs). 4-stage A32 ring
// overlaid with prologue-only B smem. A16 double-buffered; convert of tile
// t+1 interleaved into the mma loop of tile t.
// ---------------------------------------------------------------------------
#define TILE_M    32
#define RING_OFF  0            // 4 x 32768 (B fill region during prologue)
#define STG_BYTES 32768
#define A16_OFF   131072       // 2 x 16384
#define A16_BYTES 16384
#define SB1_OFF   163840
#define SW2_OFF   164864
#define PBUF_OFF  165888       // 8*32 floats
#define K1_SMEM   166912

__device__ __forceinline__ void k1_load_stage(uint32_t sb, const float* __restrict__ x,
                                              int m0, int N, int s) {
    const int tid = threadIdx.x;
    #pragma unroll
    for (int u = 0; u < 8; ++u) {
        int idx = tid + u * 256;            // 2048 16B-chunks: 32 rows x 64 f4
        int row = idx >> 6, c4 = idx & 63;
        int node = m0 + row;
        const float* src = x + (size_t)(node < N ? node : 0) * CC + c4 * 4;
        uint32_t dst = sb + RING_OFF + s * STG_BYTES + row * 1024 + c4 * 16;
        uint32_t sz = (node < N) ? 16u : 0u;
        asm volatile("cp.async.cg.shared.global [%0], [%1], 16, %2;"
                     :: "r"(dst), "l"(src), "r"(sz));
    }
}

// convert one slice (256 of 1024 fp16-16B-chunks) of A32 stage -> A16 buf
__device__ __forceinline__ void k1_conv_slice(char* sm, int srcStage, int dstBuf, int sc) {
    const int tid = threadIdx.x;
    int idx = sc * 256 + tid;
    int row = idx >> 5, c = idx & 31;
    const float4* src = (const float4*)(sm + RING_OFF + srcStage * STG_BYTES + row * 1024 + c * 32);
    float4 v0 = src[0], v1 = src[1];
    __half2 h0 = __floats2half2_rn(v0.x, v0.y), h1 = __floats2half2_rn(v0.z, v0.w);
    __half2 h2 = __floats2half2_rn(v1.x, v1.y), h3 = __floats2half2_rn(v1.z, v1.w);
    uint4 u;
    u.x = *(uint32_t*)&h0; u.y = *(uint32_t*)&h1;
    u.z = *(uint32_t*)&h2; u.w = *(uint32_t*)&h3;
    *(uint4*)(sm + A16_OFF + dstBuf * A16_BYTES + row * 512 + ((c ^ (row & 7)) << 4)) = u;
}

__global__ void __launch_bounds__(256, 1) k1_fp16(
    const float* __restrict__ x, const float* __restrict__ b1a,
    const float* __restrict__ W2a, const float* __restrict__ b2a,
    int N, int nTiles)
{
    extern __shared__ char sm[];
    const uint32_t sb = smem_u32(sm);
    float* sB1  = (float*)(sm + SB1_OFF);
    float* sW2  = (float*)(sm + SW2_OFF);
    float* pbuf = (float*)(sm + PBUF_OFF);

    const int tid  = threadIdx.x;
    const int lane = tid & 31;
    const int w    = tid >> 5;
    const int ncol0 = w * 32;

    sB1[tid] = b1a[tid];
    sW2[tid] = W2a[tid];
    const float b2 = b2a[0];

    // --- prologue: fill B smem (swizzled) in ring region, B frags -> regs ---
    #pragma unroll 4
    for (int it = 0; it < 32; ++it) {
        int idx = tid + it * 256;          // 8192 16B-chunks (256 rows x 512B)
        int row = idx >> 5, c = idx & 31;
        uint4 v = *(const uint4*)(g_Wth + (size_t)row * CC + c * 8);
        *(uint4*)(sm + RING_OFF + row * 512 + ((c ^ (row & 7)) << 4)) = v;
    }
    __syncthreads();

    const int lrow   = lane & 15;
    const int lchunk = lane >> 4;
    const int qr = lane >> 2, qc = lane & 3;

    uint32_t breg[16][2][4];
    #pragma unroll
    for (int ks = 0; ks < 16; ++ks) {
        const int kc = ks * 2 + lchunk;
        #pragma unroll
        for (int bq = 0; bq < 2; ++bq) {
            int nr = ncol0 + bq * 16 + lrow;
            uint32_t ad = sb + RING_OFF + nr * 512 + ((kc ^ (nr & 7)) << 4);
            LDMX4(breg[ks][bq][0], breg[ks][bq][1], breg[ks][bq][2], breg[ks][bq][3], ad);
        }
    }
    __syncthreads();   // B region free -> becomes A ring

    // --- prime 3 ring stages (uniform commits) ---
    #pragma unroll
    for (int j = 0; j < 3; ++j) {
        int tj = blockIdx.x + j * gridDim.x;
        if (tj < nTiles) k1_load_stage(sb, x, tj * TILE_M, N, j);
        CP_COMMIT();
    }

    // pre-loop: convert tile0 -> A16[0]
    if (blockIdx.x < nTiles) {
        CP_WAIT2();               // stage 0 resident
        __syncthreads();
        #pragma unroll
        for (int sc = 0; sc < 4; ++sc) k1_conv_slice(sm, 0, 0, sc);
    }

    int i = 0;
    for (int t = blockIdx.x; t < nTiles; t += gridDim.x, ++i) {
        const int b  = i & 1;
        const int m0 = t * TILE_M;
        const bool hasNext = (t + gridDim.x) < nTiles;

        CP_WAIT1();               // stage (i+1)&3 (tile t+1) resident
        __syncthreads();          // + A16[b] visible; pbuf free

        // prefetch tile t+3 into stage (i+3)&3; uniform commit
        {
            int tn = t + 3 * gridDim.x;
            if (tn < nTiles) k1_load_stage(sb, x, tn * TILE_M, N, (i + 3) & 3);
            CP_COMMIT();
        }

        // mma (m32 x n32/warp x k256, B from regs) with inline convert of t+1
        float acc[2][4][4];
        #pragma unroll
        for (int mt = 0; mt < 2; ++mt)
            #pragma unroll
            for (int j = 0; j < 4; ++j) {
                acc[mt][j][0] = 0.f; acc[mt][j][1] = 0.f;
                acc[mt][j][2] = 0.f; acc[mt][j][3] = 0.f;
            }
        #pragma unroll
        for (int ks = 0; ks < 16; ++ks) {
            if ((ks & 3) == 0 && hasNext)
                k1_conv_slice(sm, (i + 1) & 3, b ^ 1, ks >> 2);
            const int kc = ks * 2 + lchunk;
            uint32_t a[2][4];
            #pragma unroll
            for (int mt = 0; mt < 2; ++mt) {
                int row = mt * 16 + lrow;
                uint32_t ad = sb + A16_OFF + b * A16_BYTES + row * 512 + ((kc ^ (row & 7)) << 4);
                LDMX4(a[mt][0], a[mt][1], a[mt][2], a[mt][3], ad);
            }
            #pragma unroll
            for (int mt = 0; mt < 2; ++mt)
                #pragma unroll
                for (int bq = 0; bq < 2; ++bq) {
                    mma_f16(acc[mt][2 * bq],     a[mt], breg[ks][bq][0], breg[ks][bq][2]);
                    mma_f16(acc[mt][2 * bq + 1], a[mt], breg[ks][bq][1], breg[ks][bq][3]);
                }
        }

        // epilogue: relu -> dot W2a (warp's n32 slice)
        float p[4] = {0.f, 0.f, 0.f, 0.f};   // rows qr, qr+8, 16+qr, 24+qr
        #pragma unroll
        for (int mt = 0; mt < 2; ++mt)
            #pragma unroll
            for (int j = 0; j < 4; ++j) {
                int col = ncol0 + j * 8 + qc * 2;
                float bA = sB1[col], bB = sB1[col + 1];
                float wA = sW2[col], wB = sW2[col + 1];
                p[mt * 2]     += fmaxf(acc[mt][j][0] + bA, 0.f) * wA
                               + fmaxf(acc[mt][j][1] + bB, 0.f) * wB;
                p[mt * 2 + 1] += fmaxf(acc[mt][j][2] + bA, 0.f) * wA
                               + fmaxf(acc[mt][j][3] + bB, 0.f) * wB;
            }
        #pragma unroll
        for (int j = 0; j < 4; ++j) {
            p[j] += __shfl_xor_sync(0xffffffffu, p[j], 1);
            p[j] += __shfl_xor_sync(0xffffffffu, p[j], 2);
        }
        if (qc == 0) {
            pbuf[w * 32 + qr]      = p[0];
            pbuf[w * 32 + qr + 8]  = p[1];
            pbuf[w * 32 + qr + 16] = p[2];
            pbuf[w * 32 + qr + 24] = p[3];
        }
        __syncthreads();
        if (tid < 32) {
            float ssum = 0.f;
            #pragma unroll
            for (int k = 0; k < 8; ++k) ssum += pbuf[k * 32 + tid];
            int node = m0 + tid;
            if (node < N) g_aw[node] = 1.f / (1.f + expf(-(ssum + b2)));
        }
    }
}

// ---------------------------------------------------------------------------
// K2: segment pooling, 512 threads = 64 f4-channel groups x 8 row lanes,
// row loop UNROLLED x4 (independent loads -> MLP 4). No atomics.
// ---------------------------------------------------------------------------
__global__ void __launch_bounds__(512) k2_pool(
    const float* __restrict__ x, const void* __restrict__ batch, int N)
{
    const int g = blockIdx.x;
    __shared__ int sR[2];
    __shared__ float4 red[3][8][64];
    const int tid = threadIdx.x;
    const int cq  = tid & 63;
    const int r   = tid >> 6;     // 0..7

    if (tid == 0) {
        int lo = 0, hi = N;
        while (lo < hi) { int mid = (lo + hi) >> 1; if (bval(batch, mid) < (long long)g) lo = mid + 1; else hi = mid; }
        sR[0] = lo;
        hi = N;
        while (lo < hi) { int mid = (lo + hi) >> 1; if (bval(batch, mid) < (long long)g + 1) lo = mid + 1; else hi = mid; }
        sR[1] = lo;
    }
    __syncthreads();
    const int s = sR[0], e = sR[1];

    float4 sum = make_float4(0.f, 0.f, 0.f, 0.f);
    float4 att = make_float4(0.f, 0.f, 0.f, 0.f);
    float4 mx  = make_float4(-INFINITY, -INFINITY, -INFINITY, -INFINITY);

    int i = s + r;
    for (; i + 24 < e; i += 32) {
        float4 v0 = ((const float4*)(x + (size_t)(i)      * CC))[cq];
        float4 v1 = ((const float4*)(x + (size_t)(i + 8)  * CC))[cq];
        float4 v2 = ((const float4*)(x + (size_t)(i + 16) * CC))[cq];
        float4 v3 = ((const float4*)(x + (size_t)(i + 24) * CC))[cq];
        float w0 = g_aw[i], w1 = g_aw[i + 8], w2 = g_aw[i + 16], w3 = g_aw[i + 24];
        sum.x += v0.x + v1.x + v2.x + v3.x;
        sum.y += v0.y + v1.y + v2.y + v3.y;
        sum.z += v0.z + v1.z + v2.z + v3.z;
        sum.w += v0.w + v1.w + v2.w + v3.w;
        att.x = fmaf(v0.x, w0, fmaf(v1.x, w1, fmaf(v2.x, w2, fmaf(v3.x, w3, att.x))));
        att.y = fmaf(v0.y, w0, fmaf(v1.y, w1, fmaf(v2.y, w2, fmaf(v3.y, w3, att.y))));
        att.z = fmaf(v0.z, w0, fmaf(v1.z, w1, fmaf(v2.z, w2, fmaf(v3.z, w3, att.z))));
        att.w = fmaf(v0.w, w0, fmaf(v1.w, w1, fmaf(v2.w, w2, fmaf(v3.w, w3, att.w))));
        mx.x = fmaxf(mx.x, fmaxf(fmaxf(v0.x, v1.x), fmaxf(v2.x, v3.x)));
        mx.y = fmaxf(mx.y, fmaxf(fmaxf(v0.y, v1.y), fmaxf(v2.y, v3.y)));
        mx.z = fmaxf(mx.z, fmaxf(fmaxf(v0.z, v1.z), fmaxf(v2.z, v3.z)));
        mx.w = fmaxf(mx.w, fmaxf(fmaxf(v0.w, v1.w), fmaxf(v2.w, v3.w)));
    }
    for (; i < e; i += 8) {
        float4 v = ((const float4*)(x + (size_t)i * CC))[cq];
        float wt = g_aw[i];
        sum.x += v.x; sum.y += v.y; sum.z += v.z; sum.w += v.w;
        att.x = fmaf(v.x, wt, att.x); att.y = fmaf(v.y, wt, att.y);
        att.z = fmaf(v.z, wt, att.z); att.w = fmaf(v.w, wt, att.w);
        mx.x = fmaxf(mx.x, v.x); mx.y = fmaxf(mx.y, v.y);
        mx.z = fmaxf(mx.z, v.z); mx.w = fmaxf(mx.w, v.w);
    }
    red[0][r][cq] = sum; red[1][r][cq] = att; red[2][r][cq] = mx;
    __syncthreads();

    if (r == 0) {
        #pragma unroll
        for (int k = 1; k < 8; ++k) {
            float4 a = red[0][k][cq], b = red[1][k][cq], m = red[2][k][cq];
            sum.x += a.x; sum.y += a.y; sum.z += a.z; sum.w += a.w;
            att.x += b.x; att.y += b.y; att.z += b.z; att.w += b.w;
            mx.x = fmaxf(mx.x, m.x); mx.y = fmaxf(mx.y, m.y);
            mx.z = fmaxf(mx.z, m.z); mx.w = fmaxf(mx.w, m.w);
        }
        float inv = 1.f / fmaxf((float)(e - s), 1.f);
        float4 mean = make_float4(sum.x * inv, sum.y * inv, sum.z * inv, sum.w * inv);
        float4 mxo = (e > s) ? mx : make_float4(0.f, 0.f, 0.f, 0.f);
        float* comb = g_comb + (size_t)g * (3 * CC);
        ((float4*)(comb))[cq]          = att;
        ((float4*)(comb + CC))[cq]     = mean;
        ((float4*)(comb + 2 * CC))[cq] = mxo;
    }
}

// ---------------------------------------------------------------------------
// K3: tf32 mma GEMM with bias (+optional relu).
// CTA 128(M) x 64(N), 8 warps each own an m16 slab across all 64 cols.
// K chunked by 32; fragment mapping identical to round-2's verified kernel.
// ---------------------------------------------------------------------------
template <bool RELU>
__global__ void __launch_bounds__(256) k3t(
    const float* __restrict__ A, const float* __restrict__ B,
    const float* __restrict__ bias, float* __restrict__ Out,
    int M, int K, int Nn)
{
    __shared__ uint32_t sA[128 * 33];   // [row][k], k-stride 33
    __shared__ uint32_t sB[32 * 68];    // [k][n], n-stride 68
    const int tid  = threadIdx.x;
    const int lane = tid & 31, w = tid >> 5;
    const int qr = lane >> 2, qc = lane & 3;
    const int m0 = blockIdx.y * 128, n0 = blockIdx.x * 64;
    const int row_lo = w * 16 + qr;

    float acc[8][4] = {};

    for (int kt = 0; kt < K; kt += 32) {
        __syncthreads();
        // A chunk 128 x 32 (fp32 -> tf32)
        #pragma unroll
        for (int u = 0; u < 4; ++u) {
            int idx = tid + u * 256;        // 1024 f4
            int row = idx >> 3, c4 = idx & 7;
            float4 v = *(const float4*)(A + (size_t)(m0 + row) * K + kt + c4 * 4);
            uint32_t* d = sA + row * 33 + c4 * 4;
            d[0] = f2tf32(v.x); d[1] = f2tf32(v.y);
            d[2] = f2tf32(v.z); d[3] = f2tf32(v.w);
        }
        // B chunk 32 x 64 (fp32 -> tf32)
        #pragma unroll
        for (int u = 0; u < 2; ++u) {
            int idx = tid + u * 256;        // 512 f4
            int k = idx >> 4, n4 = idx & 15;
            float4 v = *(const float4*)(B + (size_t)(kt + k) * Nn + n0 + n4 * 4);
            uint32_t* d = sB + k * 68 + n4 * 4;
            d[0] = f2tf32(v.x); d[1] = f2tf32(v.y);
            d[2] = f2tf32(v.z); d[3] = f2tf32(v.w);
        }
        __syncthreads();
        #pragma unroll
        for (int kc = 0; kc < 4; ++kc) {
            int k0 = kc * 8;
            uint32_t a0 = sA[row_lo * 33 + k0 + qc];
            uint32_t a1 = sA[(row_lo + 8) * 33 + k0 + qc];
            uint32_t a2 = sA[row_lo * 33 + k0 + qc + 4];
            uint32_t a3 = sA[(row_lo + 8) * 33 + k0 + qc + 4];
            #pragma unroll
            for (int nc = 0; nc < 8; ++nc) {
                uint32_t b0 = sB[(k0 + qc) * 68 + nc * 8 + qr];
                uint32_t b1 = sB[(k0 + qc + 4) * 68 + nc * 8 + qr];
                mma_tf32(acc[nc], a0, a1, a2, a3, b0, b1);
            }
        }
    }

    #pragma unroll
    for (int nc = 0; nc < 8; ++nc) {
        int col = n0 + nc * 8 + qc * 2;
        float bA = bias[col], bB = bias[col + 1];
        float v00 = acc[nc][0] + bA, v01 = acc[nc][1] + bB;
        float v10 = acc[nc][2] + bA, v11 = acc[nc][3] + bB;
        if (RELU) {
            v00 = fmaxf(v00, 0.f); v01 = fmaxf(v01, 0.f);
            v10 = fmaxf(v10, 0.f); v11 = fmaxf(v11, 0.f);
        }
        int r0 = m0 + row_lo, r1 = r0 + 8;
        Out[(size_t)r0 * Nn + col]     = v00;
        Out[(size_t)r0 * Nn + col + 1] = v01;
        Out[(size_t)r1 * Nn + col]     = v10;
        Out[(size_t)r1 * Nn + col + 1] = v11;
    }
}

// ---------------------------------------------------------------------------
// launch
// ---------------------------------------------------------------------------
extern "C" void kernel_launch(void* const* d_in, const int* in_sizes, int n_in,
                              void* d_out, int out_size)
{
    const float* x     = (const float*)d_in[0];
    const void*  batch = d_in[1];
    const float* W1a   = (const float*)d_in[2];
    const float* b1a   = (const float*)d_in[3];
    const float* W2a   = (const float*)d_in[4];
    const float* b2a   = (const float*)d_in[5];
    const float* W1f   = (const float*)d_in[6];
    const float* b1f   = (const float*)d_in[7];
    const float* W2f   = (const float*)d_in[8];
    const float* b2f   = (const float*)d_in[9];
    float* out = (float*)d_out;

    const int N = in_sizes[0] / CC;
    const int G = out_size / CC;

    float *comb_ptr = nullptr, *hid_ptr = nullptr;
    cudaGetSymbolAddress((void**)&comb_ptr, g_comb);
    cudaGetSymbolAddress((void**)&hid_ptr, g_hidden);

    cudaFuncSetAttribute(k1_fp16, cudaFuncAttributeMaxDynamicSharedMemorySize, K1_SMEM);

    k0_init<<<1, 1>>>();
    k0_detect<<<(N + 255) / 256, 256>>>((const int*)batch, N);
    k_wt<<<CC, CC>>>(W1a);

    const int nTiles = (N + TILE_M - 1) / TILE_M;
    const int grid = nTiles < 148 ? nTiles : 148;
    k1_fp16<<<grid, 256, K1_SMEM>>>(x, b1a, W2a, b2a, N, nTiles);
    k2_pool<<<G, 512>>>(x, batch, N);
    k3t<true ><<<dim3(CC / 64, G / 128), 256>>>(comb_ptr, W1f, b1f, hid_ptr, G, 3 * CC, CC);
    k3t<false><<<dim3(CC / 64, G / 128), 256>>>(hid_ptr,  W2f, b2f, out,     G, CC,     CC);
}

// round 12
// speedup vs baseline: 1.1510x; 1.0753x over previous
#include <cuda_runtime.h>
#include <cuda_fp16.h>
#include <cstdint>
#include <math.h>

#define CC 256          // channels
#define GG_MAX 4096     // graphs
#define N_MAX 500000    // nodes

__device__ float g_aw[N_MAX + 256];
__device__ __align__(16) __half g_Wth[CC * CC];   // W1a^T fp16: [n][k]
__device__ float g_comb[GG_MAX * 3 * CC];
__device__ float g_hidden[GG_MAX * CC];
__device__ int   g_is64;

// ---------------------------------------------------------------------------
// helpers
// ---------------------------------------------------------------------------
__device__ __forceinline__ uint32_t smem_u32(const void* p) {
    uint32_t a;
    asm("{ .reg .u64 t; cvta.to.shared.u64 t, %1; cvt.u32.u64 %0, t; }" : "=r"(a) : "l"(p));
    return a;
}

#define LDMX4(r0, r1, r2, r3, addr) \
    asm volatile("ldmatrix.sync.aligned.m8n8.x4.shared.b16 {%0,%1,%2,%3}, [%4];" \
        : "=r"(r0), "=r"(r1), "=r"(r2), "=r"(r3) : "r"(addr))

__device__ __forceinline__ void mma_f16(float* c, const uint32_t* a, uint32_t b0, uint32_t b1) {
    asm volatile(
        "mma.sync.aligned.m16n8k16.row.col.f32.f16.f16.f32 "
        "{%0,%1,%2,%3}, {%4,%5,%6,%7}, {%8,%9}, {%0,%1,%2,%3};"
        : "+f"(c[0]), "+f"(c[1]), "+f"(c[2]), "+f"(c[3])
        : "r"(a[0]), "r"(a[1]), "r"(a[2]), "r"(a[3]), "r"(b0), "r"(b1));
}

__device__ __forceinline__ uint32_t f2tf32(float f) {
    uint32_t r;
    asm("cvt.rna.tf32.f32 %0, %1;" : "=r"(r) : "f"(f));
    return r;
}

__device__ __forceinline__ void mma_tf32(float* c,
                                         uint32_t a0, uint32_t a1, uint32_t a2, uint32_t a3,
                                         uint32_t b0, uint32_t b1) {
    asm volatile(
        "mma.sync.aligned.m16n8k8.row.col.f32.tf32.tf32.f32 "
        "{%0,%1,%2,%3}, {%4,%5,%6,%7}, {%8,%9}, {%0,%1,%2,%3};\n"
        : "+f"(c[0]), "+f"(c[1]), "+f"(c[2]), "+f"(c[3])
        : "r"(a0), "r"(a1), "r"(a2), "r"(a3), "r"(b0), "r"(b1));
}

#define CP_COMMIT() asm volatile("cp.async.commit_group;" ::: "memory")
#define CP_WAIT1()  asm volatile("cp.async.wait_group 1;" ::: "memory")
#define CP_WAIT2()  asm volatile("cp.async.wait_group 2;" ::: "memory")

// ---------------------------------------------------------------------------
// batch dtype detection (int32 vs int64 view; sorted-ness discriminates)
// ---------------------------------------------------------------------------
__global__ void k0_detect(const int* __restrict__ b32, int N) {
    int i = blockIdx.x * blockDim.x + threadIdx.x;
    if (i < N - 1) {
        int a = b32[i], b = b32[i + 1];
        if (a > b || a < 0 || b < 0) g_is64 = 1;
    }
}
__device__ __forceinline__ long long bval(const void* b, int i) {
    if (g_is64) return ((const long long*)b)[i];
    return (long long)((const int*)b)[i];
}

// ---------------------------------------------------------------------------
// W1a -> transposed fp16 (+ g_is64 reset; runs before k0_detect)
// ---------------------------------------------------------------------------
__global__ void k_wt(const float* __restrict__ W1a) {
    int n = blockIdx.x, k = threadIdx.x;
    if (n == 0 && k == 0) g_is64 = 0;
    g_Wth[n * CC + k] = __float2half(W1a[k * CC + n]);
}

// ---------------------------------------------------------------------------
// K1 (round-8 best: ~210us): fused attention MLP, fp16 mma.sync, persistent
// CTAs. B frags in registers (warp n32 slice). 4-stage A32 ring overlaid with
// prologue-only B smem. A16 double-buffered; convert of tile t+1 interleaved
// into the mma loop of tile t.
// ---------------------------------------------------------------------------
#define TILE_M    32
#define RING_OFF  0            // 4 x 32768 (B fill region during prologue)
#define STG_BYTES 32768
#define A16_OFF   131072       // 2 x 16384
#define A16_BYTES 16384
#define SB1_OFF   163840
#define SW2_OFF   164864
#define PBUF_OFF  165888       // 8*32 floats
#define K1_SMEM   166912

__device__ __forceinline__ void k1_load_stage(uint32_t sb, const float* __restrict__ x,
                                              int m0, int N, int s) {
    const int tid = threadIdx.x;
    #pragma unroll
    for (int u = 0; u < 8; ++u) {
        int idx = tid + u * 256;            // 2048 16B-chunks: 32 rows x 64 f4
        int row = idx >> 6, c4 = idx & 63;
        int node = m0 + row;
        const float* src = x + (size_t)(node < N ? node : 0) * CC + c4 * 4;
        uint32_t dst = sb + RING_OFF + s * STG_BYTES + row * 1024 + c4 * 16;
        uint32_t sz = (node < N) ? 16u : 0u;
        asm volatile("cp.async.cg.shared.global [%0], [%1], 16, %2;"
                     :: "r"(dst), "l"(src), "r"(sz));
    }
}

// convert one slice (256 of 1024 fp16-16B-chunks) of A32 stage -> A16 buf
__device__ __forceinline__ void k1_conv_slice(char* sm, int srcStage, int dstBuf, int sc) {
    const int tid = threadIdx.x;
    int idx = sc * 256 + tid;
    int row = idx >> 5, c = idx & 31;
    const float4* src = (const float4*)(sm + RING_OFF + srcStage * STG_BYTES + row * 1024 + c * 32);
    float4 v0 = src[0], v1 = src[1];
    __half2 h0 = __floats2half2_rn(v0.x, v0.y), h1 = __floats2half2_rn(v0.z, v0.w);
    __half2 h2 = __floats2half2_rn(v1.x, v1.y), h3 = __floats2half2_rn(v1.z, v1.w);
    uint4 u;
    u.x = *(uint32_t*)&h0; u.y = *(uint32_t*)&h1;
    u.z = *(uint32_t*)&h2; u.w = *(uint32_t*)&h3;
    *(uint4*)(sm + A16_OFF + dstBuf * A16_BYTES + row * 512 + ((c ^ (row & 7)) << 4)) = u;
}

__global__ void __launch_bounds__(256, 1) k1_fp16(
    const float* __restrict__ x, const float* __restrict__ b1a,
    const float* __restrict__ W2a, const float* __restrict__ b2a,
    int N, int nTiles)
{
    extern __shared__ char sm[];
    const uint32_t sb = smem_u32(sm);
    float* sB1  = (float*)(sm + SB1_OFF);
    float* sW2  = (float*)(sm + SW2_OFF);
    float* pbuf = (float*)(sm + PBUF_OFF);

    const int tid  = threadIdx.x;
    const int lane = tid & 31;
    const int w    = tid >> 5;
    const int ncol0 = w * 32;

    sB1[tid] = b1a[tid];
    sW2[tid] = W2a[tid];
    const float b2 = b2a[0];

    // --- prologue: fill B smem (swizzled) in ring region, B frags -> regs ---
    #pragma unroll 4
    for (int it = 0; it < 32; ++it) {
        int idx = tid + it * 256;          // 8192 16B-chunks (256 rows x 512B)
        int row = idx >> 5, c = idx & 31;
        uint4 v = *(const uint4*)(g_Wth + (size_t)row * CC + c * 8);
        *(uint4*)(sm + RING_OFF + row * 512 + ((c ^ (row & 7)) << 4)) = v;
    }
    __syncthreads();

    const int lrow   = lane & 15;
    const int lchunk = lane >> 4;
    const int qr = lane >> 2, qc = lane & 3;

    uint32_t breg[16][2][4];
    #pragma unroll
    for (int ks = 0; ks < 16; ++ks) {
        const int kc = ks * 2 + lchunk;
        #pragma unroll
        for (int bq = 0; bq < 2; ++bq) {
            int nr = ncol0 + bq * 16 + lrow;
            uint32_t ad = sb + RING_OFF + nr * 512 + ((kc ^ (nr & 7)) << 4);
            LDMX4(breg[ks][bq][0], breg[ks][bq][1], breg[ks][bq][2], breg[ks][bq][3], ad);
        }
    }
    __syncthreads();   // B region free -> becomes A ring

    // --- prime 3 ring stages (uniform commits) ---
    #pragma unroll
    for (int j = 0; j < 3; ++j) {
        int tj = blockIdx.x + j * gridDim.x;
        if (tj < nTiles) k1_load_stage(sb, x, tj * TILE_M, N, j);
        CP_COMMIT();
    }

    // pre-loop: convert tile0 -> A16[0]
    if (blockIdx.x < nTiles) {
        CP_WAIT2();               // stage 0 resident
        __syncthreads();
        #pragma unroll
        for (int sc = 0; sc < 4; ++sc) k1_conv_slice(sm, 0, 0, sc);
    }

    int i = 0;
    for (int t = blockIdx.x; t < nTiles; t += gridDim.x, ++i) {
        const int b  = i & 1;
        const int m0 = t * TILE_M;
        const bool hasNext = (t + gridDim.x) < nTiles;

        CP_WAIT1();               // stage (i+1)&3 (tile t+1) resident
        __syncthreads();          // + A16[b] visible; pbuf free

        // prefetch tile t+3 into stage (i+3)&3; uniform commit
        {
            int tn = t + 3 * gridDim.x;
            if (tn < nTiles) k1_load_stage(sb, x, tn * TILE_M, N, (i + 3) & 3);
            CP_COMMIT();
        }

        // mma (m32 x n32/warp x k256, B from regs) with inline convert of t+1
        float acc[2][4][4];
        #pragma unroll
        for (int mt = 0; mt < 2; ++mt)
            #pragma unroll
            for (int j = 0; j < 4; ++j) {
                acc[mt][j][0] = 0.f; acc[mt][j][1] = 0.f;
                acc[mt][j][2] = 0.f; acc[mt][j][3] = 0.f;
            }
        #pragma unroll
        for (int ks = 0; ks < 16; ++ks) {
            if ((ks & 3) == 0 && hasNext)
                k1_conv_slice(sm, (i + 1) & 3, b ^ 1, ks >> 2);
            const int kc = ks * 2 + lchunk;
            uint32_t a[2][4];
            #pragma unroll
            for (int mt = 0; mt < 2; ++mt) {
                int row = mt * 16 + lrow;
                uint32_t ad = sb + A16_OFF + b * A16_BYTES + row * 512 + ((kc ^ (row & 7)) << 4);
                LDMX4(a[mt][0], a[mt][1], a[mt][2], a[mt][3], ad);
            }
            #pragma unroll
            for (int mt = 0; mt < 2; ++mt)
                #pragma unroll
                for (int bq = 0; bq < 2; ++bq) {
                    mma_f16(acc[mt][2 * bq],     a[mt], breg[ks][bq][0], breg[ks][bq][2]);
                    mma_f16(acc[mt][2 * bq + 1], a[mt], breg[ks][bq][1], breg[ks][bq][3]);
                }
        }

        // epilogue: relu -> dot W2a (warp's n32 slice)
        float p[4] = {0.f, 0.f, 0.f, 0.f};   // rows qr, qr+8, 16+qr, 24+qr
        #pragma unroll
        for (int mt = 0; mt < 2; ++mt)
            #pragma unroll
            for (int j = 0; j < 4; ++j) {
                int col = ncol0 + j * 8 + qc * 2;
                float bA = sB1[col], bB = sB1[col + 1];
                float wA = sW2[col], wB = sW2[col + 1];
                p[mt * 2]     += fmaxf(acc[mt][j][0] + bA, 0.f) * wA
                               + fmaxf(acc[mt][j][1] + bB, 0.f) * wB;
                p[mt * 2 + 1] += fmaxf(acc[mt][j][2] + bA, 0.f) * wA
                               + fmaxf(acc[mt][j][3] + bB, 0.f) * wB;
            }
        #pragma unroll
        for (int j = 0; j < 4; ++j) {
            p[j] += __shfl_xor_sync(0xffffffffu, p[j], 1);
            p[j] += __shfl_xor_sync(0xffffffffu, p[j], 2);
        }
        if (qc == 0) {
            pbuf[w * 32 + qr]      = p[0];
            pbuf[w * 32 + qr + 8]  = p[1];
            pbuf[w * 32 + qr + 16] = p[2];
            pbuf[w * 32 + qr + 24] = p[3];
        }
        __syncthreads();
        if (tid < 32) {
            float ssum = 0.f;
            #pragma unroll
            for (int k = 0; k < 8; ++k) ssum += pbuf[k * 32 + tid];
            int node = m0 + tid;
            if (node < N) g_aw[node] = 1.f / (1.f + expf(-(ssum + b2)));
        }
    }
}

// ---------------------------------------------------------------------------
// K2: segment pooling. 512 threads = 64 float4-channel groups x 8 row lanes.
// Simple loop (round-7 measured config). No atomics, deterministic.
// ---------------------------------------------------------------------------
__global__ void __launch_bounds__(512) k2_pool(
    const float* __restrict__ x, const void* __restrict__ batch, int N)
{
    const int g = blockIdx.x;
    __shared__ int sR[2];
    __shared__ float4 red[3][8][64];
    const int tid = threadIdx.x;
    const int cq  = tid & 63;
    const int r   = tid >> 6;     // 0..7

    if (tid == 0) {
        int lo = 0, hi = N;
        while (lo < hi) { int mid = (lo + hi) >> 1; if (bval(batch, mid) < (long long)g) lo = mid + 1; else hi = mid; }
        sR[0] = lo;
        hi = N;
        while (lo < hi) { int mid = (lo + hi) >> 1; if (bval(batch, mid) < (long long)g + 1) lo = mid + 1; else hi = mid; }
        sR[1] = lo;
    }
    __syncthreads();
    const int s = sR[0], e = sR[1];

    float4 sum = make_float4(0.f, 0.f, 0.f, 0.f);
    float4 att = make_float4(0.f, 0.f, 0.f, 0.f);
    float4 mx  = make_float4(-INFINITY, -INFINITY, -INFINITY, -INFINITY);

    for (int i = s + r; i < e; i += 8) {
        float4 v = ((const float4*)(x + (size_t)i * CC))[cq];
        float wt = g_aw[i];
        sum.x += v.x; sum.y += v.y; sum.z += v.z; sum.w += v.w;
        att.x = fmaf(v.x, wt, att.x); att.y = fmaf(v.y, wt, att.y);
        att.z = fmaf(v.z, wt, att.z); att.w = fmaf(v.w, wt, att.w);
        mx.x = fmaxf(mx.x, v.x); mx.y = fmaxf(mx.y, v.y);
        mx.z = fmaxf(mx.z, v.z); mx.w = fmaxf(mx.w, v.w);
    }
    red[0][r][cq] = sum; red[1][r][cq] = att; red[2][r][cq] = mx;
    __syncthreads();

    if (r == 0) {
        #pragma unroll
        for (int k = 1; k < 8; ++k) {
            float4 a = red[0][k][cq], b = red[1][k][cq], m = red[2][k][cq];
            sum.x += a.x; sum.y += a.y; sum.z += a.z; sum.w += a.w;
            att.x += b.x; att.y += b.y; att.z += b.z; att.w += b.w;
            mx.x = fmaxf(mx.x, m.x); mx.y = fmaxf(mx.y, m.y);
            mx.z = fmaxf(mx.z, m.z); mx.w = fmaxf(mx.w, m.w);
        }
        float inv = 1.f / fmaxf((float)(e - s), 1.f);
        float4 mean = make_float4(sum.x * inv, sum.y * inv, sum.z * inv, sum.w * inv);
        float4 mxo = (e > s) ? mx : make_float4(0.f, 0.f, 0.f, 0.f);
        float* comb = g_comb + (size_t)g * (3 * CC);
        ((float4*)(comb))[cq]          = att;
        ((float4*)(comb + CC))[cq]     = mean;
        ((float4*)(comb + 2 * CC))[cq] = mxo;
    }
}

// ---------------------------------------------------------------------------
// K3: tf32 mma GEMM with bias (+optional relu).
// CTA 128(M) x 64(N), 8 warps each own an m16 slab across all 64 cols.
// ---------------------------------------------------------------------------
template <bool RELU>
__global__ void __launch_bounds__(256) k3t(
    const float* __restrict__ A, const float* __restrict__ B,
    const float* __restrict__ bias, float* __restrict__ Out,
    int M, int K, int Nn)
{
    __shared__ uint32_t sA[128 * 33];   // [row][k], k-stride 33
    __shared__ uint32_t sB[32 * 68];    // [k][n], n-stride 68
    const int tid  = threadIdx.x;
    const int lane = tid & 31, w = tid >> 5;
    const int qr = lane >> 2, qc = lane & 3;
    const int m0 = blockIdx.y * 128, n0 = blockIdx.x * 64;
    const int row_lo = w * 16 + qr;

    float acc[8][4] = {};

    for (int kt = 0; kt < K; kt += 32) {
        __syncthreads();
        // A chunk 128 x 32 (fp32 -> tf32)
        #pragma unroll
        for (int u = 0; u < 4; ++u) {
            int idx = tid + u * 256;        // 1024 f4
            int row = idx >> 3, c4 = idx & 7;
            float4 v = *(const float4*)(A + (size_t)(m0 + row) * K + kt + c4 * 4);
            uint32_t* d = sA + row * 33 + c4 * 4;
            d[0] = f2tf32(v.x); d[1] = f2tf32(v.y);
            d[2] = f2tf32(v.z); d[3] = f2tf32(v.w);
        }
        // B chunk 32 x 64 (fp32 -> tf32)
        #pragma unroll
        for (int u = 0; u < 2; ++u) {
            int idx = tid + u * 256;        // 512 f4
            int k = idx >> 4, n4 = idx & 15;
            float4 v = *(const float4*)(B + (size_t)(kt + k) * Nn + n0 + n4 * 4);
            uint32_t* d = sB + k * 68 + n4 * 4;
            d[0] = f2tf32(v.x); d[1] = f2tf32(v.y);
            d[2] = f2tf32(v.z); d[3] = f2tf32(v.w);
        }
        __syncthreads();
        #pragma unroll
        for (int kc = 0; kc < 4; ++kc) {
            int k0 = kc * 8;
            uint32_t a0 = sA[row_lo * 33 + k0 + qc];
            uint32_t a1 = sA[(row_lo + 8) * 33 + k0 + qc];
            uint32_t a2 = sA[row_lo * 33 + k0 + qc + 4];
            uint32_t a3 = sA[(row_lo + 8) * 33 + k0 + qc + 4];
            #pragma unroll
            for (int nc = 0; nc < 8; ++nc) {
                uint32_t b0 = sB[(k0 + qc) * 68 + nc * 8 + qr];
                uint32_t b1 = sB[(k0 + qc + 4) * 68 + nc * 8 + qr];
                mma_tf32(acc[nc], a0, a1, a2, a3, b0, b1);
            }
        }
    }

    #pragma unroll
    for (int nc = 0; nc < 8; ++nc) {
        int col = n0 + nc * 8 + qc * 2;
        float bA = bias[col], bB = bias[col + 1];
        float v00 = acc[nc][0] + bA, v01 = acc[nc][1] + bB;
        float v10 = acc[nc][2] + bA, v11 = acc[nc][3] + bB;
        if (RELU) {
            v00 = fmaxf(v00, 0.f); v01 = fmaxf(v01, 0.f);
            v10 = fmaxf(v10, 0.f); v11 = fmaxf(v11, 0.f);
        }
        int r0 = m0 + row_lo, r1 = r0 + 8;
        Out[(size_t)r0 * Nn + col]     = v00;
        Out[(size_t)r0 * Nn + col + 1] = v01;
        Out[(size_t)r1 * Nn + col]     = v10;
        Out[(size_t)r1 * Nn + col + 1] = v11;
    }
}

// ---------------------------------------------------------------------------
// launch
// ---------------------------------------------------------------------------
extern "C" void kernel_launch(void* const* d_in, const int* in_sizes, int n_in,
                              void* d_out, int out_size)
{
    const float* x     = (const float*)d_in[0];
    const void*  batch = d_in[1];
    const float* W1a   = (const float*)d_in[2];
    const float* b1a   = (const float*)d_in[3];
    const float* W2a   = (const float*)d_in[4];
    const float* b2a   = (const float*)d_in[5];
    const float* W1f   = (const float*)d_in[6];
    const float* b1f   = (const float*)d_in[7];
    const float* W2f   = (const float*)d_in[8];
    const float* b2f   = (const float*)d_in[9];
    float* out = (float*)d_out;

    const int N = in_sizes[0] / CC;
    const int G = out_size / CC;

    float *comb_ptr = nullptr, *hid_ptr = nullptr;
    cudaGetSymbolAddress((void**)&comb_ptr, g_comb);
    cudaGetSymbolAddress((void**)&hid_ptr, g_hidden);

    cudaFuncSetAttribute(k1_fp16, cudaFuncAttributeMaxDynamicSharedMemorySize, K1_SMEM);

    k_wt<<<CC, CC>>>(W1a);                                // also resets g_is64
    k0_detect<<<(N + 255) / 256, 256>>>((const int*)batch, N);

    const int nTiles = (N + TILE_M - 1) / TILE_M;
    const int grid = nTiles < 148 ? nTiles : 148;
    k1_fp16<<<grid, 256, K1_SMEM>>>(x, b1a, W2a, b2a, N, nTiles);
    k2_pool<<<G, 512>>>(x, batch, N);
    k3t<true ><<<dim3(CC / 64, G / 128), 256>>>(comb_ptr, W1f, b1f, hid_ptr, G, 3 * CC, CC);
    k3t<false><<<dim3(CC / 64, G / 128), 256>>>(hid_ptr,  W2f, b2f, out,     G, CC,     CC);
}